// round 13
// baseline (speedup 1.0000x reference)
#include <cuda_runtime.h>
#include <cuda_fp16.h>
#include <cstdint>

#define NROWS 131072
#define HALFN 65536
#define DDIM  512
#define HDIM  512
#define EPTN  65536

__device__ __half g_w2fh[(size_t)NROWS * HDIM];   // w2f = X@W2+b2, fp16 (128 MB)
__device__ __half g_wh[6u * 512 * 512];           // [z=mat*2+t][n][k] fp16 weights
__device__ __half g_xh[(size_t)NROWS * DDIM];     // X in fp16 (128 MB)
__device__ __half g_eh[(size_t)2 * EPTN * DDIM];  // E0|E1 in fp16 (128 MB)

// K-chunk = 64 (128B rows, SW128 swizzle). Per stage: A 16K | B 16K = 32K, x3 stages.
#define BUF_STRIDE 32768
#define OFF_A 0
#define OFF_B 16384
#define SMEM_TOTAL (3 * BUF_STRIDE)

#define SWZ128(o) ((o) ^ (((o) >> 3) & 0x70))

__device__ __forceinline__ uint32_t smem_u32(const void* p) {
    uint32_t a;
    asm("{ .reg .u64 t; cvta.to.shared.u64 t, %1; cvt.u32.u64 %0, t; }" : "=r"(a) : "l"(p));
    return a;
}
#define CPASYNC16(dst, src) asm volatile("cp.async.cg.shared.global [%0], [%1], 16;" :: "r"(dst), "l"(src))
#define CPCOMMIT() asm volatile("cp.async.commit_group;" ::: "memory")
#define CPWAIT0()  asm volatile("cp.async.wait_group 0;" ::: "memory")
#define CPWAIT1()  asm volatile("cp.async.wait_group 1;" ::: "memory")
#define LDSM4(r0, r1, r2, r3, ad) \
    asm volatile("ldmatrix.sync.aligned.m8n8.x4.shared.b16 {%0,%1,%2,%3}, [%4];" \
        : "=r"(r0), "=r"(r1), "=r"(r2), "=r"(r3) : "r"(ad))
#define MMA(d, a, b0, b1) \
    asm volatile("mma.sync.aligned.m16n8k16.row.col.f32.f16.f16.f32 " \
        "{%0,%1,%2,%3}, {%4,%5,%6,%7}, {%8,%9}, {%0,%1,%2,%3};" \
        : "+f"((d)[0]), "+f"((d)[1]), "+f"((d)[2]), "+f"((d)[3]) \
        : "r"((a)[0]), "r"((a)[1]), "r"((a)[2]), "r"((a)[3]), "r"(b0), "r"(b1))
#define REDV2(p, x, y) \
    asm volatile("red.global.add.v2.f32 [%0], {%1, %2};" :: "l"(p), "f"(x), "f"(y) : "memory")

__device__ __forceinline__ uint32_t pack_h2(float a, float b) {
    __half2 h = __floats2half2_rn(a, b);
    return *(uint32_t*)&h;
}

// Streaming fp32 -> fp16 convert (same _rn rounding as the old in-loop pack)
__global__ void convert_fp16(const float4* __restrict__ src, __half2* __restrict__ dst,
                             int n4) {
    int i = blockIdx.x * blockDim.x + threadIdx.x;
    if (i < n4) {
        float4 v = src[i];
        uint2 o = {pack_h2(v.x, v.y), pack_h2(v.z, v.w)};
        *(uint2*)(dst + 2 * (size_t)i) = o;
    }
}

// Transpose W1/W2/W5 into [z][n][k] fp16
__global__ void prep_weights(const float* __restrict__ W1, const float* __restrict__ W2,
                             const float* __restrict__ W5) {
    __shared__ float tile[32][33];
    int z = blockIdx.z, mat = z >> 1, t = z & 1;
    const float* W = (mat == 0 ? W1 : mat == 1 ? W2 : W5) + (size_t)t * 512 * 512;
    int n0 = blockIdx.x * 32, k0 = blockIdx.y * 32;
    int lx = threadIdx.x & 31, ly = threadIdx.x >> 5;
    #pragma unroll
    for (int i = 0; i < 32; i += 8)
        tile[ly + i][lx] = W[(size_t)(k0 + ly + i) * 512 + n0 + lx];
    __syncthreads();
    size_t base = ((size_t)z * 512 + n0) * 512 + k0;
    #pragma unroll
    for (int i = 0; i < 32; i += 8)
        g_wh[base + (size_t)(ly + i) * 512 + lx] = __float2half_rn(tile[lx][ly + i]);
}

// EDGE=false: fused dual-proj. bx in [0,8): mat = bx>>2 (0 -> W1/out(f32), 1 -> W2/w2f(f16)).
// EDGE=true : merged edge sets. by>>9 = set; GEMM(E_set@W5[set]) + gather/scatter epilogue.
template<bool EDGE>
__global__ __launch_bounds__(256, 2)
void mma_gemm(const float* __restrict__ bias1, const float* __restrict__ bias2,
              float* __restrict__ out,
              const int* __restrict__ e0, const int* __restrict__ e1)
{
    extern __shared__ char smem[];
    const uint32_t sb = smem_u32(smem);
    const int tid = threadIdx.x, wid = tid >> 5, lane = tid & 31;
    const int bx = blockIdx.x, by = blockIdx.y;
    const int set = EDGE ? (by >> 9) : 0;
    const int ry = (EDGE ? (by & 511) : by) * 128;
    const int cx = (EDGE ? bx : (bx & 3)) * 128;
    const int mat = EDGE ? 2 : (bx >> 2);
    const int t = EDGE ? set : (ry >= HALFN ? 1 : 0);
    const int z = mat * 2 + t;
    const __half* Ah = EDGE ? (g_eh + (size_t)set * EPTN * DDIM) : g_xh;
    const int* edges = EDGE ? (set ? e1 : e0) : nullptr;
    const int wm = wid & 3, wn = wid >> 2;   // warp tile (wm*32, wn*64)

    // ---- cp.async fill mappings: 1 thr per half-row (64B), 4 x 16B copies ----
    const int arow = tid >> 1, ahalf = tid & 1;
    const __half* AhG = Ah + (size_t)(ry + arow) * DDIM + ahalf * 32;
    const __half* BhG = g_wh + ((size_t)z * 512 + cx + arow) * 512 + ahalf * 32;
    // base has k-bits 5:6 == 0, so SWZ128(base + q*16) == SWZ128(base) ^ (q*16)
    const uint32_t fd0 = SWZ128(arow * 128 + ahalf * 64);

    // ---- ldmatrix per-lane BASE offsets; per-ks offset = base ^ (ks*32) ----
    uint32_t a_base[2];
    #pragma unroll
    for (int mt = 0; mt < 2; mt++)
        a_base[mt] = SWZ128((wm * 32 + mt * 16 + (lane & 15)) * 128 + (lane >> 4) * 16);
    uint32_t b_base[4];
    #pragma unroll
    for (int p = 0; p < 4; p++)
        b_base[p] = SWZ128((wn * 64 + p * 16 + (lane & 7) + ((lane & 16) ? 8 : 0)) * 128 +
                           ((lane & 8) ? 16 : 0));

    float d[2][8][4];
    #pragma unroll
    for (int i = 0; i < 2; i++)
        #pragma unroll
        for (int j = 0; j < 8; j++)
            #pragma unroll
            for (int q = 0; q < 4; q++) d[i][j][q] = 0.f;

    // ---- prologue: issue stages for chunks 0 and 1 (K=64 each) ----
    #pragma unroll
    for (int j = 0; j < 2; j++) {
        const uint32_t bb = sb + j * BUF_STRIDE;
        #pragma unroll
        for (int q = 0; q < 4; q++) {
            CPASYNC16(bb + OFF_A + (fd0 ^ (q * 16)), AhG + j * 64 + q * 8);
            CPASYNC16(bb + OFF_B + (fd0 ^ (q * 16)), BhG + j * 64 + q * 8);
        }
        CPCOMMIT();
    }

    int bufi = 0, nbufi = 2;   // buffer of chunk c; buffer for chunk c+2
    for (int c = 0; c < 8; c++) {
        if (c < 7) CPWAIT1(); else CPWAIT0();
        __syncthreads();

        if (c < 6) {
            const uint32_t bb = sb + nbufi * BUF_STRIDE;
            #pragma unroll
            for (int q = 0; q < 4; q++) {
                CPASYNC16(bb + OFF_A + (fd0 ^ (q * 16)), AhG + (c + 2) * 64 + q * 8);
                CPASYNC16(bb + OFF_B + (fd0 ^ (q * 16)), BhG + (c + 2) * 64 + q * 8);
            }
            CPCOMMIT();
        }

        // ---- compute chunk c: plain fp16 D += A*B, 4 k16 slices ----
        const uint32_t buf = sb + bufi * BUF_STRIDE;
        #pragma unroll
        for (int ks = 0; ks < 4; ks++) {
            const uint32_t kx = ks * 32;
            uint32_t aF[2][4], bh[4][4];
            #pragma unroll
            for (int mt = 0; mt < 2; mt++)
                LDSM4(aF[mt][0], aF[mt][1], aF[mt][2], aF[mt][3],
                      buf + OFF_A + (a_base[mt] ^ kx));
            #pragma unroll
            for (int p = 0; p < 4; p++)
                LDSM4(bh[p][0], bh[p][1], bh[p][2], bh[p][3],
                      buf + OFF_B + (b_base[p] ^ kx));
            #pragma unroll
            for (int p = 0; p < 4; p++)
                #pragma unroll
                for (int mt = 0; mt < 2; mt++) {
                    MMA(d[mt][2 * p],     aF[mt], bh[p][0], bh[p][1]);
                    MMA(d[mt][2 * p + 1], aF[mt], bh[p][2], bh[p][3]);
                }
        }

        bufi = (bufi == 2) ? 0 : bufi + 1;
        nbufi = (nbufi == 2) ? 0 : nbufi + 1;
    }

    // ---- epilogue ----
    const float* bt = (EDGE ? bias1 : (mat ? bias2 : bias1)) + (size_t)t * HDIM;
    const int c2 = (lane & 3) * 2, gr = lane >> 2;
    const int colw = cx + wn * 64 + c2;
    float2 bv[8];
    #pragma unroll
    for (int n8 = 0; n8 < 8; n8++)
        bv[n8] = *(const float2*)(bt + colw + n8 * 8);

    if (!EDGE) {
        #pragma unroll
        for (int mt = 0; mt < 2; mt++) {
            const int r0 = ry + wm * 32 + mt * 16 + gr;
            if (mat == 0) {
                float* p0 = out + (size_t)r0 * HDIM + colw;
                float* p1 = p0 + (size_t)8 * HDIM;
                #pragma unroll
                for (int n8 = 0; n8 < 8; n8++) {
                    *(float2*)(p0 + n8 * 8) = make_float2(d[mt][n8][0] + bv[n8].x,
                                                          d[mt][n8][1] + bv[n8].y);
                    *(float2*)(p1 + n8 * 8) = make_float2(d[mt][n8][2] + bv[n8].x,
                                                          d[mt][n8][3] + bv[n8].y);
                }
            } else {
                __half* p0 = g_w2fh + (size_t)r0 * HDIM + colw;
                __half* p1 = p0 + (size_t)8 * HDIM;
                #pragma unroll
                for (int n8 = 0; n8 < 8; n8++) {
                    *(__half2*)(p0 + n8 * 8) = __floats2half2_rn(d[mt][n8][0] + bv[n8].x,
                                                                 d[mt][n8][1] + bv[n8].y);
                    *(__half2*)(p1 + n8 * 8) = __floats2half2_rn(d[mt][n8][2] + bv[n8].x,
                                                                 d[mt][n8][3] + bv[n8].y);
                }
            }
        }
    } else {
        #pragma unroll
        for (int mt = 0; mt < 2; mt++) {
            const int e0i = ry + wm * 32 + mt * 16 + gr;
            const int2 ea = ((const int2*)edges)[e0i];
            const int2 eb = ((const int2*)edges)[e0i + 8];
            const __half* wa = g_w2fh + (size_t)ea.y * HDIM + colw;
            const __half* wb = g_w2fh + (size_t)eb.y * HDIM + colw;
            float* oa = out + (size_t)ea.x * HDIM + colw;
            float* ob = out + (size_t)eb.x * HDIM + colw;
            #pragma unroll
            for (int n8 = 0; n8 < 8; n8++) {
                float2 ga = __half22float2(*(const __half2*)(wa + n8 * 8));
                float2 gb = __half22float2(*(const __half2*)(wb + n8 * 8));
                REDV2(oa + n8 * 8, d[mt][n8][0] + bv[n8].x + ga.x,
                                   d[mt][n8][1] + bv[n8].y + ga.y);
                REDV2(ob + n8 * 8, d[mt][n8][2] + bv[n8].x + gb.x,
                                   d[mt][n8][3] + bv[n8].y + gb.y);
            }
        }
    }
}

extern "C" void kernel_launch(void* const* d_in, const int* in_sizes, int n_in,
                              void* d_out, int out_size)
{
    const float* X  = (const float*)d_in[0];
    const float* E0 = (const float*)d_in[1];
    const float* E1 = (const float*)d_in[2];
    const float* W1 = (const float*)d_in[3];
    const float* b1 = (const float*)d_in[4];
    const float* W2 = (const float*)d_in[5];
    const float* b2 = (const float*)d_in[6];
    const float* W5 = (const float*)d_in[11];
    const float* b5 = (const float*)d_in[12];
    const int* edges0 = (const int*)d_in[13];   // JAX x64-disabled: int32 pairs
    const int* edges1 = (const int*)d_in[14];
    float* out = (float*)d_out;

    __half *xh = nullptr, *eh = nullptr;
    cudaGetSymbolAddress((void**)&xh, g_xh);
    cudaGetSymbolAddress((void**)&eh, g_eh);

    cudaFuncSetAttribute(mma_gemm<false>, cudaFuncAttributeMaxDynamicSharedMemorySize, SMEM_TOTAL);
    cudaFuncSetAttribute(mma_gemm<true>,  cudaFuncAttributeMaxDynamicSharedMemorySize, SMEM_TOTAL);

    // fp32 -> fp16 streaming converts (X, E0, E1)
    const int n4x = NROWS * DDIM / 4;          // 16M float4
    const int n4e = EPTN * DDIM / 4;           // 8M float4
    convert_fp16<<<n4x / 256, 256>>>((const float4*)X, (__half2*)xh, n4x);
    convert_fp16<<<n4e / 256, 256>>>((const float4*)E0, (__half2*)eh, n4e);
    convert_fp16<<<n4e / 256, 256>>>((const float4*)E1,
                                     (__half2*)(eh + (size_t)EPTN * DDIM), n4e);
    prep_weights<<<dim3(16, 16, 6), 256>>>(W1, W2, W5);

    // Fused: out = X@W1[t] + b1[t]  AND  w2f(fp16) = X@W2[t] + b2[t]
    mma_gemm<false><<<dim3(8, 1024), 256, SMEM_TOTAL>>>(b1, b2, out, nullptr, nullptr);
    // Merged edge sets: out[src] += (E@W5[t] + b5[t]) + w2f[dst]  (softmax singleton = 1)
    mma_gemm<true><<<dim3(4, 1024), 256, SMEM_TOTAL>>>(b5, nullptr, out, edges0, edges1);
}